// round 7
// baseline (speedup 1.0000x reference)
#include <cuda_runtime.h>
#include <cuda_fp16.h>
#include <cstdint>

// ---------------- problem constants ----------------
#define L_Q   13343
#define BLMAX 26686          // B=2 * L_Q
#define CDIM  256

__constant__ int c_HW[5]    = {100, 50, 25, 13, 7};
__constant__ int c_start[5] = {0, 10000, 12500, 13125, 13294};

// ---------------- scratch (static device globals; no allocs) ----------------
__device__ float  g_value[(size_t)BLMAX * 256];
__device__ float  g_off  [(size_t)BLMAX * 320];
__device__ float  g_attn [(size_t)BLMAX * 160];
__device__ float  g_acc  [(size_t)BLMAX * 256];
__device__ float  g_src2 [(size_t)BLMAX * 256];
__device__ float  g_x    [(size_t)BLMAX * 256];
__device__ __half g_h    [(size_t)BLMAX * 2048];
__device__ float  g_y    [(size_t)BLMAX * 256];

// ---------------- fp16 mma helper ----------------
__device__ __forceinline__ void mma_f16(float* d, const uint32_t* a, const uint32_t* b) {
    asm volatile(
        "mma.sync.aligned.m16n8k16.row.col.f32.f16.f16.f32 "
        "{%0,%1,%2,%3}, {%4,%5,%6,%7}, {%8,%9}, {%0,%1,%2,%3};\n"
        : "+f"(d[0]), "+f"(d[1]), "+f"(d[2]), "+f"(d[3])
        : "r"(a[0]), "r"(a[1]), "r"(a[2]), "r"(a[3]), "r"(b[0]), "r"(b[1]));
}

__device__ __forceinline__ uint32_t pack_half2(float lo, float hi) {
    __half2 h = __floats2half2_rn(lo, hi);
    return *(uint32_t*)&h;
}

// ---------------- FP16 tensor-core GEMM: C = act((A (+A2)) @ W + bias) ----------------
// Block tile 128x128, BK=32 halves (16 k-pairs), 256 threads = 8 warps (2x4),
// warp tile 64x32, per warp 4x4 m16n8k16 tiles. Double-buffered smem,
// uint32 = half2 along k. Stride 136 => conflict-free fragment LDS.
#define TBM 128
#define TBN 128
#define TBK 32              // halves per k-step
#define KP  16              // k-pairs per step
#define TPAD 8
#define TSTR (TBM + TPAD)

template<bool ADD_A, bool RELU, bool A_HALF, bool OUT_HALF>
__global__ __launch_bounds__(256, 2)
void gemm_f16(const void* __restrict__ Araw, const float* __restrict__ A2,
              const float* __restrict__ W, const float* __restrict__ bias,
              void* __restrict__ Craw, int M, int N, int K)
{
    __shared__ uint32_t As[2][KP][TSTR];   // [kpair][row] = half2(A[row][2k],A[row][2k+1])
    __shared__ uint32_t Bs[2][KP][TSTR];   // [kpair][col] = half2(W[2k][col],W[2k+1][col])

    const int tid  = threadIdx.x;
    const int lane = tid & 31;
    const int warp = tid >> 5;
    const int wm = (warp >> 2) * 64;
    const int wn = (warp & 3) * 32;
    const int bm = blockIdx.y * TBM;
    const int bn = blockIdx.x * TBN;

    const float*  Af = (const float*)Araw;
    const __half* Ah = (const __half*)Araw;

    // A loader: 128 rows x 32 halves; 4 vectors (of 4 k-values) per thread
    int arow[4], acol[4]; bool aval[4];
#pragma unroll
    for (int i = 0; i < 4; i++) {
        int v = tid + 256 * i;
        arow[i] = v >> 3;            // 8 vectors per row
        acol[i] = (v & 7) * 4;       // k offset (halves/floats)
        aval[i] = (bm + arow[i]) < M;
    }
    // B loader: 16 k-pairs x 128 cols; 2 pair-vectors per thread
    int bpair[2], bcol[2]; bool bvalid[2];
#pragma unroll
    for (int i = 0; i < 2; i++) {
        int v = tid + 256 * i;
        bpair[i] = v >> 5;           // 32 vectors per pair-row
        bcol[i]  = (v & 31) * 4;
        bvalid[i] = (bn + bcol[i]) < N;
    }

    float acc[4][4][4];
#pragma unroll
    for (int a = 0; a < 4; a++)
#pragma unroll
        for (int b = 0; b < 4; b++)
#pragma unroll
            for (int c = 0; c < 4; c++) acc[a][b][c] = 0.f;

    uint32_t areg[4][2];   // 2 half2 per vector
    uint32_t breg[2][4];   // 4 half2 per pair-vector

    auto LDG = [&](int k0) {
#pragma unroll
        for (int i = 0; i < 4; i++) {
            if (aval[i]) {
                if (A_HALF) {
                    const __half* p = Ah + (size_t)(bm + arow[i]) * K + k0 + acol[i];
                    uint2 u = *(const uint2*)p;
                    areg[i][0] = u.x; areg[i][1] = u.y;
                } else {
                    const float* p = Af + (size_t)(bm + arow[i]) * K + k0 + acol[i];
                    float4 v = *(const float4*)p;
                    if (ADD_A) {
                        const float4 u = *(const float4*)(A2 + (size_t)(bm + arow[i]) * K + k0 + acol[i]);
                        v.x += u.x; v.y += u.y; v.z += u.z; v.w += u.w;
                    }
                    areg[i][0] = pack_half2(v.x, v.y);
                    areg[i][1] = pack_half2(v.z, v.w);
                }
            } else { areg[i][0] = 0u; areg[i][1] = 0u; }
        }
#pragma unroll
        for (int i = 0; i < 2; i++) {
            if (bvalid[i]) {
                const float* p0 = W + (size_t)(k0 + 2 * bpair[i]) * N + bn + bcol[i];
                const float* p1 = p0 + N;
                float4 r0 = *(const float4*)p0;
                float4 r1 = *(const float4*)p1;
                breg[i][0] = pack_half2(r0.x, r1.x);
                breg[i][1] = pack_half2(r0.y, r1.y);
                breg[i][2] = pack_half2(r0.z, r1.z);
                breg[i][3] = pack_half2(r0.w, r1.w);
            } else {
                breg[i][0] = breg[i][1] = breg[i][2] = breg[i][3] = 0u;
            }
        }
    };

    auto STS = [&](int s) {
#pragma unroll
        for (int i = 0; i < 4; i++) {
            As[s][acol[i] / 2 + 0][arow[i]] = areg[i][0];
            As[s][acol[i] / 2 + 1][arow[i]] = areg[i][1];
        }
#pragma unroll
        for (int i = 0; i < 2; i++)
            *(uint4*)&Bs[s][bpair[i]][bcol[i]] = *(uint4*)breg[i];
    };

    auto COMPUTE = [&](int s) {
        const int r = lane >> 2, c = lane & 3;
#pragma unroll
        for (int kc = 0; kc < KP; kc += 8) {
            uint32_t af[4][4], bf[4][2];
#pragma unroll
            for (int mt = 0; mt < 4; mt++) {
                int rr = wm + mt * 16 + r;
                af[mt][0] = As[s][kc + c][rr];
                af[mt][1] = As[s][kc + c][rr + 8];
                af[mt][2] = As[s][kc + c + 4][rr];
                af[mt][3] = As[s][kc + c + 4][rr + 8];
            }
#pragma unroll
            for (int nt = 0; nt < 4; nt++) {
                int cc = wn + nt * 8 + r;
                bf[nt][0] = Bs[s][kc + c][cc];
                bf[nt][1] = Bs[s][kc + c + 4][cc];
            }
#pragma unroll
            for (int mt = 0; mt < 4; mt++)
#pragma unroll
                for (int nt = 0; nt < 4; nt++)
                    mma_f16(acc[mt][nt], af[mt], bf[nt]);
        }
    };

    LDG(0); STS(0); __syncthreads();
    int s = 0;
    for (int k0 = TBK; k0 < K + TBK; k0 += TBK) {
        const bool more = (k0 < K);
        if (more) LDG(k0);
        COMPUTE(s);
        if (more) {
            STS(s ^ 1);
            __syncthreads();
            s ^= 1;
        }
    }

    // epilogue
    float*  Cf = (float*)Craw;
    __half* Ch = (__half*)Craw;
    const int r = lane >> 2, c2 = (lane & 3) * 2;
#pragma unroll
    for (int mt = 0; mt < 4; mt++) {
        const int r0 = bm + wm + mt * 16 + r;
#pragma unroll
        for (int nt = 0; nt < 4; nt++) {
            const int cc = bn + wn + nt * 8 + c2;
            if (cc < N) {
                const float b0 = bias[cc], b1 = bias[cc + 1];
#pragma unroll
                for (int hh = 0; hh < 2; hh++) {
                    const int rr = r0 + hh * 8;
                    if (rr < M) {
                        float ox = acc[mt][nt][hh * 2 + 0] + b0;
                        float oy = acc[mt][nt][hh * 2 + 1] + b1;
                        if (RELU) { ox = fmaxf(ox, 0.f); oy = fmaxf(oy, 0.f); }
                        if (OUT_HALF) {
                            __half2 o = __floats2half2_rn(ox, oy);
                            *(__half2*)&Ch[(size_t)rr * N + cc] = o;
                        } else {
                            *(float2*)&Cf[(size_t)rr * N + cc] = make_float2(ox, oy);
                        }
                    }
                }
            }
        }
    }
}

// ---------------- deformable sampling ----------------
// 256-thread block = 4 queries; per query 64 threads: head h = (t>>3)&7? -> use
// subgroup of 64: thread = (head = (t&63)>>3, channel group ((t&63)&7)*4).
__global__ __launch_bounds__(256)
void sample_kernel(const float* __restrict__ value,   // [B, L, 256]
                   const float* __restrict__ ref,     // [B, L, 5, 2]
                   const float* __restrict__ off,     // [B*L, 320]
                   const float* __restrict__ logits,  // [B*L, 160]
                   float* __restrict__ acc_out,       // [B*L, 256]
                   int M)
{
    const int sub = threadIdx.x >> 6;          // 0..3
    const int t   = threadIdx.x & 63;
    const int q   = blockIdx.x * 4 + sub;

    __shared__ float s_off[4][320];
    __shared__ float s_log[4][160];
    __shared__ float s_ref[4][10];

    if (q < M) {
#pragma unroll
        for (int i = t; i < 320; i += 64) s_off[sub][i] = off[(size_t)q * 320 + i];
#pragma unroll
        for (int i = t; i < 160; i += 64) s_log[sub][i] = logits[(size_t)q * 160 + i];
        if (t < 10) s_ref[sub][t] = ref[(size_t)q * 10 + t];
    }
    __syncthreads();
    if (q >= M) return;

    const int b  = q / L_Q;
    const int h  = t >> 3;
    const int ci = (t & 7) * 4;

    float m = -1e30f;
#pragma unroll
    for (int p = 0; p < 20; p++) m = fmaxf(m, s_log[sub][h * 20 + p]);
    float e[20], ssum = 0.f;
#pragma unroll
    for (int p = 0; p < 20; p++) { e[p] = __expf(s_log[sub][h * 20 + p] - m); ssum += e[p]; }
    const float inv = 1.0f / ssum;

    float4 a = make_float4(0.f, 0.f, 0.f, 0.f);
    const float* vbase = value + (size_t)b * L_Q * 256 + h * 32 + ci;

#pragma unroll
    for (int l = 0; l < 5; l++) {
        const int Hs = c_HW[l], Ws = c_HW[l];
        const float* vlvl = vbase + (size_t)c_start[l] * 256;
        const float rx = s_ref[sub][l * 2 + 0];
        const float ry = s_ref[sub][l * 2 + 1];
#pragma unroll
        for (int p = 0; p < 4; p++) {
            const float ox = s_off[sub][h * 40 + l * 8 + p * 2 + 0];
            const float oy = s_off[sub][h * 40 + l * 8 + p * 2 + 1];
            const float w  = e[l * 4 + p] * inv;

            const float locx = rx + ox / (float)Ws;
            const float locy = ry + oy / (float)Hs;
            const float px = locx * (float)Ws - 0.5f;
            const float py = locy * (float)Hs - 0.5f;

            const float x0f = floorf(px), y0f = floorf(py);
            const float lx = px - x0f, ly = py - y0f;
            const int x0 = (int)x0f, y0 = (int)y0f;
            const int x1 = x0 + 1,  y1 = y0 + 1;

            const bool vx0 = (x0 >= 0) & (x0 < Ws);
            const bool vx1 = (x1 >= 0) & (x1 < Ws);
            const bool vy0 = (y0 >= 0) & (y0 < Hs);
            const bool vy1 = (y1 >= 0) & (y1 < Hs);

            if (vx0 & vy0) {
                const float cw = w * (1.f - lx) * (1.f - ly);
                float4 v = *(const float4*)(vlvl + (size_t)(y0 * Ws + x0) * 256);
                a.x = fmaf(cw, v.x, a.x); a.y = fmaf(cw, v.y, a.y);
                a.z = fmaf(cw, v.z, a.z); a.w = fmaf(cw, v.w, a.w);
            }
            if (vx1 & vy0) {
                const float cw = w * lx * (1.f - ly);
                float4 v = *(const float4*)(vlvl + (size_t)(y0 * Ws + x1) * 256);
                a.x = fmaf(cw, v.x, a.x); a.y = fmaf(cw, v.y, a.y);
                a.z = fmaf(cw, v.z, a.z); a.w = fmaf(cw, v.w, a.w);
            }
            if (vx0 & vy1) {
                const float cw = w * (1.f - lx) * ly;
                float4 v = *(const float4*)(vlvl + (size_t)(y1 * Ws + x0) * 256);
                a.x = fmaf(cw, v.x, a.x); a.y = fmaf(cw, v.y, a.y);
                a.z = fmaf(cw, v.z, a.z); a.w = fmaf(cw, v.w, a.w);
            }
            if (vx1 & vy1) {
                const float cw = w * lx * ly;
                float4 v = *(const float4*)(vlvl + (size_t)(y1 * Ws + x1) * 256);
                a.x = fmaf(cw, v.x, a.x); a.y = fmaf(cw, v.y, a.y);
                a.z = fmaf(cw, v.z, a.z); a.w = fmaf(cw, v.w, a.w);
            }
        }
    }
    *(float4*)&acc_out[(size_t)q * 256 + h * 32 + ci] = a;
}

// ---------------- fused add + layernorm ----------------
__global__ __launch_bounds__(256)
void add_ln_kernel(const float* __restrict__ a, const float* __restrict__ b,
                   const float* __restrict__ g, const float* __restrict__ be,
                   float* __restrict__ out, int M)
{
    const int warp = threadIdx.x >> 5;
    const int lane = threadIdx.x & 31;
    const int row  = blockIdx.x * 8 + warp;
    if (row >= M) return;

    const float* ar = a + (size_t)row * 256;
    const float* br = b + (size_t)row * 256;

    float4 v0 = *(const float4*)(ar + lane * 4);
    float4 v1 = *(const float4*)(ar + 128 + lane * 4);
    float4 w0 = *(const float4*)(br + lane * 4);
    float4 w1 = *(const float4*)(br + 128 + lane * 4);

    float v[8];
    v[0] = v0.x + w0.x; v[1] = v0.y + w0.y; v[2] = v0.z + w0.z; v[3] = v0.w + w0.w;
    v[4] = v1.x + w1.x; v[5] = v1.y + w1.y; v[6] = v1.z + w1.z; v[7] = v1.w + w1.w;

    float s = 0.f, sq = 0.f;
#pragma unroll
    for (int i = 0; i < 8; i++) { s += v[i]; sq = fmaf(v[i], v[i], sq); }
#pragma unroll
    for (int o = 16; o; o >>= 1) {
        s  += __shfl_xor_sync(0xffffffffu, s,  o);
        sq += __shfl_xor_sync(0xffffffffu, sq, o);
    }
    const float mean = s * (1.f / 256.f);
    const float var  = sq * (1.f / 256.f) - mean * mean;
    const float inv  = rsqrtf(var + 1e-5f);

    float* orow = out + (size_t)row * 256;
#pragma unroll
    for (int half = 0; half < 2; half++) {
        int c = half * 128 + lane * 4;
        float4 o;
        float* vv = v + half * 4;
        o.x = (vv[0] - mean) * inv * g[c + 0] + be[c + 0];
        o.y = (vv[1] - mean) * inv * g[c + 1] + be[c + 1];
        o.z = (vv[2] - mean) * inv * g[c + 2] + be[c + 2];
        o.w = (vv[3] - mean) * inv * g[c + 3] + be[c + 3];
        *(float4*)&orow[c] = o;
    }
}

// ---------------- launch ----------------
static inline dim3 tgrid(int M, int N) {
    return dim3((N + TBN - 1) / TBN, (M + TBM - 1) / TBM);
}

extern "C" void kernel_launch(void* const* d_in, const int* in_sizes, int n_in,
                              void* d_out, int out_size)
{
    const float* src  = (const float*)d_in[0];
    const float* pos  = (const float*)d_in[1];
    const float* ref  = (const float*)d_in[2];
    const float* wv   = (const float*)d_in[3];
    const float* bv   = (const float*)d_in[4];
    const float* wo   = (const float*)d_in[5];
    const float* bo   = (const float*)d_in[6];
    const float* wa   = (const float*)d_in[7];
    const float* ba   = (const float*)d_in[8];
    const float* wout = (const float*)d_in[9];
    const float* bout = (const float*)d_in[10];
    const float* ln1g = (const float*)d_in[11];
    const float* ln1b = (const float*)d_in[12];
    const float* w1   = (const float*)d_in[13];
    const float* b1   = (const float*)d_in[14];
    const float* w2   = (const float*)d_in[15];
    const float* b2   = (const float*)d_in[16];
    const float* ln2g = (const float*)d_in[17];
    const float* ln2b = (const float*)d_in[18];
    float* out = (float*)d_out;

    const int M = in_sizes[0] / CDIM;   // B*L = 26686

    float *value, *offp, *attnp, *accp, *src2, *xp, *yp;
    __half* hp;
    cudaGetSymbolAddress((void**)&value, g_value);
    cudaGetSymbolAddress((void**)&offp,  g_off);
    cudaGetSymbolAddress((void**)&attnp, g_attn);
    cudaGetSymbolAddress((void**)&accp,  g_acc);
    cudaGetSymbolAddress((void**)&src2,  g_src2);
    cudaGetSymbolAddress((void**)&xp,    g_x);
    cudaGetSymbolAddress((void**)&hp,    g_h);
    cudaGetSymbolAddress((void**)&yp,    g_y);

    // 1) value = src @ wv + bv
    gemm_f16<false, false, false, false><<<tgrid(M, 256), 256>>>(src, nullptr, wv, bv, value, M, 256, 256);
    // 2) offsets = (src+pos) @ wo + bo
    gemm_f16<true, false, false, false><<<tgrid(M, 320), 256>>>(src, pos, wo, bo, offp, M, 320, 256);
    // 3) attn logits = (src+pos) @ wa + ba
    gemm_f16<true, false, false, false><<<tgrid(M, 160), 256>>>(src, pos, wa, ba, attnp, M, 160, 256);
    // 4) deformable sampling -> acc
    sample_kernel<<<(M + 3) / 4, 256>>>(value, ref, offp, attnp, accp, M);
    // 5) src2 = acc @ wout + bout
    gemm_f16<false, false, false, false><<<tgrid(M, 256), 256>>>(accp, nullptr, wout, bout, src2, M, 256, 256);
    // 6) x = LN(src + src2)
    add_ln_kernel<<<(M + 7) / 8, 256>>>(src, src2, ln1g, ln1b, xp, M);
    // 7) h = relu(x @ w1 + b1)  -> fp16
    gemm_f16<false, true, false, true><<<tgrid(M, 2048), 256>>>(xp, nullptr, w1, b1, hp, M, 2048, 256);
    // 8) y = h @ w2 + b2  (A is fp16)
    gemm_f16<false, false, true, false><<<tgrid(M, 256), 256>>>(hp, nullptr, w2, b2, yp, M, 256, 2048);
    // 9) out = LN(x + y)
    add_ln_kernel<<<(M + 7) / 8, 256>>>(xp, yp, ln2g, ln2b, out, M);
}

// round 9
// speedup vs baseline: 1.5606x; 1.5606x over previous
#include <cuda_runtime.h>
#include <cstdint>

// ---------------- problem constants ----------------
#define L_Q   13343
#define BLMAX 26686
#define CDIM  256

__constant__ int c_HW[5]    = {100, 50, 25, 13, 7};
__constant__ int c_start[5] = {0, 10000, 12500, 13125, 13294};

// ---------------- scratch (static device globals; no allocs) ----------------
__device__ float g_q    [(size_t)BLMAX * 256];
__device__ float g_value[(size_t)BLMAX * 256];
__device__ float g_off  [(size_t)BLMAX * 320];
__device__ float g_attn [(size_t)BLMAX * 160];
__device__ float g_acc  [(size_t)BLMAX * 256];
__device__ float g_src2 [(size_t)BLMAX * 256];
__device__ float g_x    [(size_t)BLMAX * 256];
__device__ float g_h    [(size_t)BLMAX * 2048];
__device__ float g_y    [(size_t)BLMAX * 256];

// ---------------- ptx helpers ----------------
__device__ __forceinline__ uint32_t s2u(const void* p) {
    uint32_t a;
    asm("{ .reg .u64 t; cvta.to.shared.u64 t, %1; cvt.u32.u64 %0, t; }" : "=r"(a) : "l"(p));
    return a;
}
__device__ __forceinline__ void cp16(uint32_t s, const void* g) {
    asm volatile("cp.async.cg.shared.global [%0], [%1], 16;\n" :: "r"(s), "l"(g));
}
__device__ __forceinline__ void cp16z(uint32_t s, const void* g, uint32_t bytes) {
    asm volatile("cp.async.cg.shared.global [%0], [%1], 16, %2;\n"
                 :: "r"(s), "l"(g), "r"(bytes));
}
__device__ __forceinline__ void cpcommit() { asm volatile("cp.async.commit_group;\n" ::: "memory"); }
template<int N> __device__ __forceinline__ void cpwait() {
    asm volatile("cp.async.wait_group %0;\n" :: "n"(N) : "memory");
}
__device__ __forceinline__ void mma_tf32(float* d, const uint32_t* a, const uint32_t* b) {
    asm volatile(
        "mma.sync.aligned.m16n8k8.row.col.f32.tf32.tf32.f32 "
        "{%0,%1,%2,%3}, {%4,%5,%6,%7}, {%8,%9}, {%0,%1,%2,%3};\n"
        : "+f"(d[0]), "+f"(d[1]), "+f"(d[2]), "+f"(d[3])
        : "r"(a[0]), "r"(a[1]), "r"(a[2]), "r"(a[3]), "r"(b[0]), "r"(b[1]));
}

// ---------------- cp.async pipelined TF32 GEMM ----------------
// C[M][N] = act(A[M][K] @ W[K][N] + bias)
// 128x128 block tile, BK=16, 4 stages, 256 thr = 8 warps (2x4), warp 64x32.
// A smem: [row][k] stride 20 words; B smem: [k][n] stride 136 words.
// fp32 bits fed directly as tf32 operands (HW truncates mantissa).
#define PBK     16
#define PSTAGES 4
#define ASTR    20
#define BSTR    136
#define A_ST_BYTES (128 * ASTR * 4)          // 10240
#define B_ST_BYTES (PBK * BSTR * 4)          // 8704
#define SMEM_GEMM  (PSTAGES * (A_ST_BYTES + B_ST_BYTES))   // 75776

template<bool RELU>
__global__ __launch_bounds__(256, 2)
void gemm_pipe(const float* __restrict__ A, const float* __restrict__ W,
               const float* __restrict__ bias, float* __restrict__ C,
               int M, int N, int K)
{
    extern __shared__ float smem[];
    const uint32_t sbA = s2u(smem);
    const uint32_t sbB = sbA + PSTAGES * A_ST_BYTES;
    float* fA = smem;
    float* fB = smem + PSTAGES * (A_ST_BYTES / 4);

    const int tid  = threadIdx.x;
    const int lane = tid & 31;
    const int warp = tid >> 5;
    const int wm = (warp >> 2) * 64;
    const int wn = (warp & 3) * 32;
    const int bm = blockIdx.y * 128;
    const int bn = blockIdx.x * 128;
    const int NK = K / PBK;

    float acc[4][4][4];
#pragma unroll
    for (int a = 0; a < 4; a++)
#pragma unroll
        for (int b = 0; b < 4; b++)
#pragma unroll
            for (int c = 0; c < 4; c++) acc[a][b][c] = 0.f;

    auto loadc = [&](int kc, int st) {
        // A: 128 rows x 16 k = 512 x 16B, 2 vectors/thread
#pragma unroll
        for (int i = 0; i < 2; i++) {
            const int idx = tid + 256 * i;
            const int row = idx >> 2, seg = idx & 3;
            int gr = bm + row; gr = gr < M ? gr : M - 1;
            cp16(sbA + st * A_ST_BYTES + row * (ASTR * 4) + seg * 16,
                 A + (size_t)gr * K + kc * PBK + seg * 4);
        }
        // B: 16 k x 128 n = 512 x 16B, 2 vectors/thread
#pragma unroll
        for (int i = 0; i < 2; i++) {
            const int idx = tid + 256 * i;
            const int kr = idx >> 5, seg = idx & 31;
            const int col = bn + seg * 4;
            int rem = N - col;
            uint32_t bytes = rem >= 4 ? 16u : (rem > 0 ? (uint32_t)rem * 4u : 0u);
            cp16z(sbB + st * B_ST_BYTES + kr * (BSTR * 4) + seg * 16,
                  W + (size_t)(kc * PBK + kr) * N + col, bytes);
        }
        cpcommit();
    };

#pragma unroll
    for (int p = 0; p < PSTAGES - 1; p++) loadc(p, p);

    const int r = lane >> 2, c = lane & 3;

    for (int kc = 0; kc < NK; kc++) {
        const int st = kc & (PSTAGES - 1);
        {
            const int rem = NK - 1 - kc;
            if (rem >= 2) cpwait<2>(); else if (rem == 1) cpwait<1>(); else cpwait<0>();
        }
        __syncthreads();
        const int nxt = kc + PSTAGES - 1;
        if (nxt < NK) loadc(nxt, nxt & (PSTAGES - 1));

        const float* As = fA + st * (A_ST_BYTES / 4);
        const float* Bs = fB + st * (B_ST_BYTES / 4);
#pragma unroll
        for (int kcs = 0; kcs < PBK; kcs += 8) {
            uint32_t af[4][4], bf[4][2];
#pragma unroll
            for (int mt = 0; mt < 4; mt++) {
                const int rr = wm + mt * 16 + r;
                af[mt][0] = __float_as_uint(As[(rr) * ASTR + kcs + c]);
                af[mt][1] = __float_as_uint(As[(rr + 8) * ASTR + kcs + c]);
                af[mt][2] = __float_as_uint(As[(rr) * ASTR + kcs + c + 4]);
                af[mt][3] = __float_as_uint(As[(rr + 8) * ASTR + kcs + c + 4]);
            }
#pragma unroll
            for (int nt = 0; nt < 4; nt++) {
                const int cc = wn + nt * 8 + r;
                bf[nt][0] = __float_as_uint(Bs[(kcs + c) * BSTR + cc]);
                bf[nt][1] = __float_as_uint(Bs[(kcs + c + 4) * BSTR + cc]);
            }
#pragma unroll
            for (int mt = 0; mt < 4; mt++)
#pragma unroll
                for (int nt = 0; nt < 4; nt++)
                    mma_tf32(acc[mt][nt], af[mt], bf[nt]);
        }
    }

    // epilogue
    const int c2 = (lane & 3) * 2;
#pragma unroll
    for (int mt = 0; mt < 4; mt++) {
        const int r0 = bm + wm + mt * 16 + r;
#pragma unroll
        for (int nt = 0; nt < 4; nt++) {
            const int cc = bn + wn + nt * 8 + c2;
            if (cc < N) {
                const float b0 = bias[cc], b1 = bias[cc + 1];
#pragma unroll
                for (int hh = 0; hh < 2; hh++) {
                    const int rr = r0 + hh * 8;
                    if (rr < M) {
                        float ox = acc[mt][nt][hh * 2 + 0] + b0;
                        float oy = acc[mt][nt][hh * 2 + 1] + b1;
                        if (RELU) { ox = fmaxf(ox, 0.f); oy = fmaxf(oy, 0.f); }
                        *(float2*)&C[(size_t)rr * N + cc] = make_float2(ox, oy);
                    }
                }
            }
        }
    }
}

// ---------------- elementwise q = src + pos ----------------
__global__ __launch_bounds__(256)
void addvec_kernel(const float4* __restrict__ a, const float4* __restrict__ b,
                   float4* __restrict__ o, int n4)
{
    int i = blockIdx.x * 256 + threadIdx.x;
    if (i < n4) {
        float4 x = a[i], y = b[i];
        o[i] = make_float4(x.x + y.x, x.y + y.y, x.z + y.z, x.w + y.w);
    }
}

// ---------------- deformable sampling (64 threads/query) ----------------
__global__ __launch_bounds__(64)
void sample_kernel(const float* __restrict__ value,
                   const float* __restrict__ ref,
                   const float* __restrict__ off,
                   const float* __restrict__ logits,
                   float* __restrict__ acc_out)
{
    const int q = blockIdx.x;
    const int b = q / L_Q;
    const int t = threadIdx.x;

    __shared__ float s_off[320];
    __shared__ float s_log[160];
    __shared__ float s_ref[10];

#pragma unroll
    for (int i = t; i < 320; i += 64) s_off[i] = off[(size_t)q * 320 + i];
#pragma unroll
    for (int i = t; i < 160; i += 64) s_log[i] = logits[(size_t)q * 160 + i];
    if (t < 10) s_ref[t] = ref[(size_t)q * 10 + t];
    __syncthreads();

    const int h  = t >> 3;
    const int ci = (t & 7) * 4;

    float m = -1e30f;
#pragma unroll
    for (int p = 0; p < 20; p++) m = fmaxf(m, s_log[h * 20 + p]);
    float e[20], ssum = 0.f;
#pragma unroll
    for (int p = 0; p < 20; p++) { e[p] = __expf(s_log[h * 20 + p] - m); ssum += e[p]; }
    const float inv = 1.0f / ssum;

    float4 a = make_float4(0.f, 0.f, 0.f, 0.f);
    const float* vbase = value + (size_t)b * L_Q * 256 + h * 32 + ci;

#pragma unroll
    for (int l = 0; l < 5; l++) {
        const int Hs = c_HW[l], Ws = c_HW[l];
        const float* vlvl = vbase + (size_t)c_start[l] * 256;
        const float rx = s_ref[l * 2 + 0];
        const float ry = s_ref[l * 2 + 1];
#pragma unroll
        for (int p = 0; p < 4; p++) {
            const float ox = s_off[h * 40 + l * 8 + p * 2 + 0];
            const float oy = s_off[h * 40 + l * 8 + p * 2 + 1];
            const float w  = e[l * 4 + p] * inv;

            const float locx = rx + ox / (float)Ws;
            const float locy = ry + oy / (float)Hs;
            const float px = locx * (float)Ws - 0.5f;
            const float py = locy * (float)Hs - 0.5f;

            const float x0f = floorf(px), y0f = floorf(py);
            const float lx = px - x0f, ly = py - y0f;
            const int x0 = (int)x0f, y0 = (int)y0f;
            const int x1 = x0 + 1,  y1 = y0 + 1;

            const bool vx0 = (x0 >= 0) & (x0 < Ws);
            const bool vx1 = (x1 >= 0) & (x1 < Ws);
            const bool vy0 = (y0 >= 0) & (y0 < Hs);
            const bool vy1 = (y1 >= 0) & (y1 < Hs);

            if (vx0 & vy0) {
                const float cw = w * (1.f - lx) * (1.f - ly);
                float4 v = *(const float4*)(vlvl + (size_t)(y0 * Ws + x0) * 256);
                a.x = fmaf(cw, v.x, a.x); a.y = fmaf(cw, v.y, a.y);
                a.z = fmaf(cw, v.z, a.z); a.w = fmaf(cw, v.w, a.w);
            }
            if (vx1 & vy0) {
                const float cw = w * lx * (1.f - ly);
                float4 v = *(const float4*)(vlvl + (size_t)(y0 * Ws + x1) * 256);
                a.x = fmaf(cw, v.x, a.x); a.y = fmaf(cw, v.y, a.y);
                a.z = fmaf(cw, v.z, a.z); a.w = fmaf(cw, v.w, a.w);
            }
            if (vx0 & vy1) {
                const float cw = w * (1.f - lx) * ly;
                float4 v = *(const float4*)(vlvl + (size_t)(y1 * Ws + x0) * 256);
                a.x = fmaf(cw, v.x, a.x); a.y = fmaf(cw, v.y, a.y);
                a.z = fmaf(cw, v.z, a.z); a.w = fmaf(cw, v.w, a.w);
            }
            if (vx1 & vy1) {
                const float cw = w * lx * ly;
                float4 v = *(const float4*)(vlvl + (size_t)(y1 * Ws + x1) * 256);
                a.x = fmaf(cw, v.x, a.x); a.y = fmaf(cw, v.y, a.y);
                a.z = fmaf(cw, v.z, a.z); a.w = fmaf(cw, v.w, a.w);
            }
        }
    }
    *(float4*)&acc_out[(size_t)q * 256 + h * 32 + ci] = a;
}

// ---------------- fused add + layernorm ----------------
__global__ __launch_bounds__(256)
void add_ln_kernel(const float* __restrict__ a, const float* __restrict__ b,
                   const float* __restrict__ g, const float* __restrict__ be,
                   float* __restrict__ out, int M)
{
    const int warp = threadIdx.x >> 5;
    const int lane = threadIdx.x & 31;
    const int row  = blockIdx.x * 8 + warp;
    if (row >= M) return;

    const float* ar = a + (size_t)row * 256;
    const float* br = b + (size_t)row * 256;

    float4 v0 = *(const float4*)(ar + lane * 4);
    float4 v1 = *(const float4*)(ar + 128 + lane * 4);
    float4 w0 = *(const float4*)(br + lane * 4);
    float4 w1 = *(const float4*)(br + 128 + lane * 4);

    float v[8];
    v[0] = v0.x + w0.x; v[1] = v0.y + w0.y; v[2] = v0.z + w0.z; v[3] = v0.w + w0.w;
    v[4] = v1.x + w1.x; v[5] = v1.y + w1.y; v[6] = v1.z + w1.z; v[7] = v1.w + w1.w;

    float s = 0.f, sq = 0.f;
#pragma unroll
    for (int i = 0; i < 8; i++) { s += v[i]; sq = fmaf(v[i], v[i], sq); }
#pragma unroll
    for (int o = 16; o; o >>= 1) {
        s  += __shfl_xor_sync(0xffffffffu, s,  o);
        sq += __shfl_xor_sync(0xffffffffu, sq, o);
    }
    const float mean = s * (1.f / 256.f);
    const float var  = sq * (1.f / 256.f) - mean * mean;
    const float inv  = rsqrtf(var + 1e-5f);

    float* orow = out + (size_t)row * 256;
#pragma unroll
    for (int half = 0; half < 2; half++) {
        int c = half * 128 + lane * 4;
        float4 o;
        float* vv = v + half * 4;
        o.x = (vv[0] - mean) * inv * g[c + 0] + be[c + 0];
        o.y = (vv[1] - mean) * inv * g[c + 1] + be[c + 1];
        o.z = (vv[2] - mean) * inv * g[c + 2] + be[c + 2];
        o.w = (vv[3] - mean) * inv * g[c + 3] + be[c + 3];
        *(float4*)&orow[c] = o;
    }
}

// ---------------- launch ----------------
extern "C" void kernel_launch(void* const* d_in, const int* in_sizes, int n_in,
                              void* d_out, int out_size)
{
    const float* src  = (const float*)d_in[0];
    const float* pos  = (const float*)d_in[1];
    const float* ref  = (const float*)d_in[2];
    const float* wv   = (const float*)d_in[3];
    const float* bv   = (const float*)d_in[4];
    const float* wo   = (const float*)d_in[5];
    const float* bo   = (const float*)d_in[6];
    const float* wa   = (const float*)d_in[7];
    const float* ba   = (const float*)d_in[8];
    const float* wout = (const float*)d_in[9];
    const float* bout = (const float*)d_in[10];
    const float* ln1g = (const float*)d_in[11];
    const float* ln1b = (const float*)d_in[12];
    const float* w1   = (const float*)d_in[13];
    const float* b1   = (const float*)d_in[14];
    const float* w2   = (const float*)d_in[15];
    const float* b2   = (const float*)d_in[16];
    const float* ln2g = (const float*)d_in[17];
    const float* ln2b = (const float*)d_in[18];
    float* out = (float*)d_out;

    const int M  = in_sizes[0] / CDIM;       // 26686
    const int mt = (M + 127) / 128;          // 209

    float *qp, *value, *offp, *attnp, *accp, *src2, *xp, *hp, *yp;
    cudaGetSymbolAddress((void**)&qp,    g_q);
    cudaGetSymbolAddress((void**)&value, g_value);
    cudaGetSymbolAddress((void**)&offp,  g_off);
    cudaGetSymbolAddress((void**)&attnp, g_attn);
    cudaGetSymbolAddress((void**)&accp,  g_acc);
    cudaGetSymbolAddress((void**)&src2,  g_src2);
    cudaGetSymbolAddress((void**)&xp,    g_x);
    cudaGetSymbolAddress((void**)&hp,    g_h);
    cudaGetSymbolAddress((void**)&yp,    g_y);

    cudaFuncSetAttribute(gemm_pipe<false>, cudaFuncAttributeMaxDynamicSharedMemorySize, SMEM_GEMM);
    cudaFuncSetAttribute(gemm_pipe<true>,  cudaFuncAttributeMaxDynamicSharedMemorySize, SMEM_GEMM);

    // q = src + pos
    const int n4 = M * 64;
    addvec_kernel<<<(n4 + 255) / 256, 256>>>((const float4*)src, (const float4*)pos,
                                             (float4*)qp, n4);

    // 1) value = src @ wv + bv
    gemm_pipe<false><<<dim3(2, mt), 256, SMEM_GEMM>>>(src, wv, bv, value, M, 256, 256);
    // 2) offsets = q @ wo + bo
    gemm_pipe<false><<<dim3(3, mt), 256, SMEM_GEMM>>>(qp, wo, bo, offp, M, 320, 256);
    // 3) attn logits = q @ wa + ba
    gemm_pipe<false><<<dim3(2, mt), 256, SMEM_GEMM>>>(qp, wa, ba, attnp, M, 160, 256);
    // 4) deformable sampling
    sample_kernel<<<M, 64>>>(value, ref, offp, attnp, accp);
    // 5) src2 = acc @ wout + bout
    gemm_pipe<false><<<dim3(2, mt), 256, SMEM_GEMM>>>(accp, wout, bout, src2, M, 256, 256);
    // 6) x = LN(src + src2)
    add_ln_kernel<<<(M + 7) / 8, 256>>>(src, src2, ln1g, ln1b, xp, M);
    // 7) h = relu(x @ w1 + b1)
    gemm_pipe<true><<<dim3(16, mt), 256, SMEM_GEMM>>>(xp, w1, b1, hp, M, 2048, 256);
    // 8) y = h @ w2 + b2
    gemm_pipe<false><<<dim3(2, mt), 256, SMEM_GEMM>>>(hp, w2, b2, yp, M, 256, 2048);
    // 9) out = LN(x + y)
    add_ln_kernel<<<(M + 7) / 8, 256>>>(xp, yp, ln2g, ln2b, out, M);
}

// round 11
// speedup vs baseline: 2.2425x; 1.4369x over previous
#include <cuda_runtime.h>
#include <cuda_fp16.h>
#include <cstdint>

// ---------------- problem constants ----------------
#define L_Q   13343
#define BLMAX 26686
#define CDIM  256

__constant__ int c_HW[5]    = {100, 50, 25, 13, 7};
__constant__ int c_start[5] = {0, 10000, 12500, 13125, 13294};

// ---------------- scratch (static device globals; no allocs) ----------------
__device__ float    g_value[(size_t)BLMAX * 256];
__device__ float    g_off  [(size_t)BLMAX * 320];
__device__ float    g_attn [(size_t)BLMAX * 160];
__device__ float    g_src2 [(size_t)BLMAX * 256];
__device__ float    g_x    [(size_t)BLMAX * 256];
__device__ float    g_y    [(size_t)BLMAX * 256];
// fp16 activations
__device__ uint32_t g_src16[(size_t)BLMAX * 128];   // half2 [M][128]
__device__ uint32_t g_q16  [(size_t)BLMAX * 128];
__device__ uint32_t g_acc16[(size_t)BLMAX * 128];
__device__ uint32_t g_x16  [(size_t)BLMAX * 128];
__device__ uint32_t g_h16  [(size_t)BLMAX * 1024];  // half2 [M][1024]
// fp16 weights, k-pair interleaved: Wp[kp][n] = half2(W[2kp][n], W[2kp+1][n])
__device__ uint32_t g_wvp  [128 * 256];
__device__ uint32_t g_wop  [128 * 320];
__device__ uint32_t g_wap  [128 * 160];
__device__ uint32_t g_woutp[128 * 256];
__device__ uint32_t g_w1p  [128 * 2048];
__device__ uint32_t g_w2p  [1024 * 256];

// ---------------- ptx helpers ----------------
__device__ __forceinline__ uint32_t s2u(const void* p) {
    uint32_t a;
    asm("{ .reg .u64 t; cvta.to.shared.u64 t, %1; cvt.u32.u64 %0, t; }" : "=r"(a) : "l"(p));
    return a;
}
__device__ __forceinline__ void cp16(uint32_t s, const void* g) {
    asm volatile("cp.async.cg.shared.global [%0], [%1], 16;\n" :: "r"(s), "l"(g));
}
__device__ __forceinline__ void cp16z(uint32_t s, const void* g, uint32_t bytes) {
    asm volatile("cp.async.cg.shared.global [%0], [%1], 16, %2;\n"
                 :: "r"(s), "l"(g), "r"(bytes));
}
__device__ __forceinline__ void cpcommit() { asm volatile("cp.async.commit_group;\n" ::: "memory"); }
template<int N> __device__ __forceinline__ void cpwait() {
    asm volatile("cp.async.wait_group %0;\n" :: "n"(N) : "memory");
}
__device__ __forceinline__ void mma_f16(float* d, const uint32_t* a, const uint32_t* b) {
    asm volatile(
        "mma.sync.aligned.m16n8k16.row.col.f32.f16.f16.f32 "
        "{%0,%1,%2,%3}, {%4,%5,%6,%7}, {%8,%9}, {%0,%1,%2,%3};\n"
        : "+f"(d[0]), "+f"(d[1]), "+f"(d[2]), "+f"(d[3])
        : "r"(a[0]), "r"(a[1]), "r"(a[2]), "r"(a[3]), "r"(b[0]), "r"(b[1]));
}
__device__ __forceinline__ uint32_t packh2(float lo, float hi) {
    __half2 h = __floats2half2_rn(lo, hi);
    return *(uint32_t*)&h;
}

// ---------------- cp.async pipelined FP16 GEMM ----------------
// C[M][N] = act(A16[M][K] @ W + bias); W given pair-interleaved Wp[K/2][N] (half2).
// 128x128 block tile, BK=32 halves (16 kpairs), 4 stages, 256 thr = 8 warps (2x4),
// warp 64x32, m16n8k16. A smem [row][kp] stride 20 u32; B smem [kp][n] stride 136 u32.
#define KPC 16                              // kpairs per stage
#define ASTRH 20
#define BSTRH 136
#define A_STB (128 * ASTRH * 4)             // 10240
#define B_STB (KPC * BSTRH * 4)             // 8704
#define NSTG  4
#define SMEM_GEMM (NSTG * (A_STB + B_STB))  // 75776

template<bool RELU, bool OUT_HALF>
__global__ __launch_bounds__(256, 2)
void gemm_h(const __half* __restrict__ A16, const uint32_t* __restrict__ Wp,
            const float* __restrict__ bias, void* __restrict__ Craw,
            int M, int N, int K)
{
    extern __shared__ uint32_t smem[];
    const uint32_t sbA = s2u(smem);
    const uint32_t sbB = sbA + NSTG * A_STB;
    uint32_t* uA = smem;
    uint32_t* uB = smem + NSTG * (A_STB / 4);

    const int tid  = threadIdx.x;
    const int lane = tid & 31;
    const int warp = tid >> 5;
    const int wm = (warp >> 2) * 64;
    const int wn = (warp & 3) * 32;
    const int bm = blockIdx.y * 128;
    const int bn = blockIdx.x * 128;
    const int NK = K >> 5;                  // k-chunks of 32 halves

    float acc[4][4][4];
#pragma unroll
    for (int a = 0; a < 4; a++)
#pragma unroll
        for (int b = 0; b < 4; b++)
#pragma unroll
            for (int c = 0; c < 4; c++) acc[a][b][c] = 0.f;

    auto loadc = [&](int kc, int st) {
        // A: 128 rows x 64B (32 halves) = 512 x 16B -> 2 cp/thread
#pragma unroll
        for (int i = 0; i < 2; i++) {
            const int idx = tid + 256 * i;
            const int row = idx >> 2, seg = idx & 3;
            int gr = bm + row; gr = gr < M ? gr : M - 1;
            cp16(sbA + st * A_STB + row * (ASTRH * 4) + seg * 16,
                 (const char*)A16 + ((size_t)gr * K + kc * 32 + seg * 8) * 2);
        }
        // B: 16 kp x 128 cols(u32) = 512 x 16B -> 2 cp/thread
#pragma unroll
        for (int i = 0; i < 2; i++) {
            const int idx = tid + 256 * i;
            const int kr = idx >> 5, seg = idx & 31;
            const int col = bn + seg * 4;
            const int rem = N - col;
            const uint32_t bytes = rem >= 4 ? 16u : (rem > 0 ? (uint32_t)rem * 4u : 0u);
            cp16z(sbB + st * B_STB + kr * (BSTRH * 4) + seg * 16,
                  Wp + (size_t)(kc * KPC + kr) * N + col, bytes);
        }
        cpcommit();
    };

#pragma unroll
    for (int p = 0; p < NSTG - 1; p++) loadc(p, p);

    const int r = lane >> 2, c = lane & 3;

    for (int kc = 0; kc < NK; kc++) {
        const int st = kc & (NSTG - 1);
        {
            const int rem = NK - 1 - kc;
            if (rem >= 2) cpwait<2>(); else if (rem == 1) cpwait<1>(); else cpwait<0>();
        }
        __syncthreads();
        const int nxt = kc + NSTG - 1;
        if (nxt < NK) loadc(nxt, nxt & (NSTG - 1));

        const uint32_t* As = uA + st * (A_STB / 4);
        const uint32_t* Bs = uB + st * (B_STB / 4);
#pragma unroll
        for (int ks = 0; ks < KPC; ks += 8) {       // two m16n8k16 k-steps
            uint32_t af[4][4], bf[4][2];
#pragma unroll
            for (int mt = 0; mt < 4; mt++) {
                const int rr = wm + mt * 16 + r;
                af[mt][0] = As[(rr) * ASTRH + ks + c];
                af[mt][1] = As[(rr + 8) * ASTRH + ks + c];
                af[mt][2] = As[(rr) * ASTRH + ks + c + 4];
                af[mt][3] = As[(rr + 8) * ASTRH + ks + c + 4];
            }
#pragma unroll
            for (int nt = 0; nt < 4; nt++) {
                const int cc = wn + nt * 8 + r;
                bf[nt][0] = Bs[(ks + c) * BSTRH + cc];
                bf[nt][1] = Bs[(ks + c + 4) * BSTRH + cc];
            }
#pragma unroll
            for (int mt = 0; mt < 4; mt++)
#pragma unroll
                for (int nt = 0; nt < 4; nt++)
                    mma_f16(acc[mt][nt], af[mt], bf[nt]);
        }
    }

    // epilogue
    float*  Cf = (float*)Craw;
    __half* Ch = (__half*)Craw;
    const int c2 = (lane & 3) * 2;
#pragma unroll
    for (int mt = 0; mt < 4; mt++) {
        const int r0 = bm + wm + mt * 16 + r;
#pragma unroll
        for (int nt = 0; nt < 4; nt++) {
            const int cc = bn + wn + nt * 8 + c2;
            if (cc < N) {
                const float b0 = bias[cc], b1 = bias[cc + 1];
#pragma unroll
                for (int hh = 0; hh < 2; hh++) {
                    const int rr = r0 + hh * 8;
                    if (rr < M) {
                        float ox = acc[mt][nt][hh * 2 + 0] + b0;
                        float oy = acc[mt][nt][hh * 2 + 1] + b1;
                        if (RELU) { ox = fmaxf(ox, 0.f); oy = fmaxf(oy, 0.f); }
                        if (OUT_HALF) {
                            *(uint32_t*)&Ch[(size_t)rr * N + cc] = packh2(ox, oy);
                        } else {
                            *(float2*)&Cf[(size_t)rr * N + cc] = make_float2(ox, oy);
                        }
                    }
                }
            }
        }
    }
}

// ---------------- conversion kernels ----------------
__global__ __launch_bounds__(256)
void f32_to_h2(const float2* __restrict__ in, uint32_t* __restrict__ out, int n) {
    int i = blockIdx.x * 256 + threadIdx.x;
    if (i < n) { float2 v = in[i]; out[i] = packh2(v.x, v.y); }
}
__global__ __launch_bounds__(256)
void addf32_to_h2(const float2* __restrict__ a, const float2* __restrict__ b,
                  uint32_t* __restrict__ out, int n) {
    int i = blockIdx.x * 256 + threadIdx.x;
    if (i < n) { float2 x = a[i], y = b[i]; out[i] = packh2(x.x + y.x, x.y + y.y); }
}
// Wp[kp][n] = half2(W[2kp][n], W[2kp+1][n])
__global__ __launch_bounds__(256)
void w_to_pairs(const float* __restrict__ W, uint32_t* __restrict__ Wp, int KP, int N) {
    int i = blockIdx.x * 256 + threadIdx.x;
    if (i < KP * N) {
        int kp = i / N, n = i - kp * N;
        Wp[i] = packh2(W[(size_t)(2 * kp) * N + n], W[(size_t)(2 * kp + 1) * N + n]);
    }
}

// ---------------- deformable sampling (64 threads/query, fp16 out) ----------------
__global__ __launch_bounds__(64)
void sample_kernel(const float* __restrict__ value,
                   const float* __restrict__ ref,
                   const float* __restrict__ off,
                   const float* __restrict__ logits,
                   uint32_t* __restrict__ acc16)      // half2 [M][128]
{
    const int q = blockIdx.x;
    const int b = q / L_Q;
    const int t = threadIdx.x;

    __shared__ float s_off[320];
    __shared__ float s_log[160];
    __shared__ float s_ref[10];

#pragma unroll
    for (int i = t; i < 320; i += 64) s_off[i] = off[(size_t)q * 320 + i];
#pragma unroll
    for (int i = t; i < 160; i += 64) s_log[i] = logits[(size_t)q * 160 + i];
    if (t < 10) s_ref[t] = ref[(size_t)q * 10 + t];
    __syncthreads();

    const int h  = t >> 3;
    const int ci = (t & 7) * 4;

    float m = -1e30f;
#pragma unroll
    for (int p = 0; p < 20; p++) m = fmaxf(m, s_log[h * 20 + p]);
    float e[20], ssum = 0.f;
#pragma unroll
    for (int p = 0; p < 20; p++) { e[p] = __expf(s_log[h * 20 + p] - m); ssum += e[p]; }
    const float inv = 1.0f / ssum;

    float4 a = make_float4(0.f, 0.f, 0.f, 0.f);
    const float* vbase = value + (size_t)b * L_Q * 256 + h * 32 + ci;

#pragma unroll
    for (int l = 0; l < 5; l++) {
        const int Hs = c_HW[l], Ws = c_HW[l];
        const float* vlvl = vbase + (size_t)c_start[l] * 256;
        const float rx = s_ref[l * 2 + 0];
        const float ry = s_ref[l * 2 + 1];
#pragma unroll
        for (int p = 0; p < 4; p++) {
            const float ox = s_off[h * 40 + l * 8 + p * 2 + 0];
            const float oy = s_off[h * 40 + l * 8 + p * 2 + 1];
            const float w  = e[l * 4 + p] * inv;

            const float locx = rx + ox / (float)Ws;
            const float locy = ry + oy / (float)Hs;
            const float px = locx * (float)Ws - 0.5f;
            const float py = locy * (float)Hs - 0.5f;

            const float x0f = floorf(px), y0f = floorf(py);
            const float lx = px - x0f, ly = py - y0f;
            const int x0 = (int)x0f, y0 = (int)y0f;
            const int x1 = x0 + 1,  y1 = y0 + 1;

            const bool vx0 = (x0 >= 0) & (x0 < Ws);
            const bool vx1 = (x1 >= 0) & (x1 < Ws);
            const bool vy0 = (y0 >= 0) & (y0 < Hs);
            const bool vy1 = (y1 >= 0) & (y1 < Hs);

            if (vx0 & vy0) {
                const float cw = w * (1.f - lx) * (1.f - ly);
                float4 v = *(const float4*)(vlvl + (size_t)(y0 * Ws + x0) * 256);
                a.x = fmaf(cw, v.x, a.x); a.y = fmaf(cw, v.y, a.y);
                a.z = fmaf(cw, v.z, a.z); a.w = fmaf(cw, v.w, a.w);
            }
            if (vx1 & vy0) {
                const float cw = w * lx * (1.f - ly);
                float4 v = *(const float4*)(vlvl + (size_t)(y0 * Ws + x1) * 256);
                a.x = fmaf(cw, v.x, a.x); a.y = fmaf(cw, v.y, a.y);
                a.z = fmaf(cw, v.z, a.z); a.w = fmaf(cw, v.w, a.w);
            }
            if (vx0 & vy1) {
                const float cw = w * (1.f - lx) * ly;
                float4 v = *(const float4*)(vlvl + (size_t)(y1 * Ws + x0) * 256);
                a.x = fmaf(cw, v.x, a.x); a.y = fmaf(cw, v.y, a.y);
                a.z = fmaf(cw, v.z, a.z); a.w = fmaf(cw, v.w, a.w);
            }
            if (vx1 & vy1) {
                const float cw = w * lx * ly;
                float4 v = *(const float4*)(vlvl + (size_t)(y1 * Ws + x1) * 256);
                a.x = fmaf(cw, v.x, a.x); a.y = fmaf(cw, v.y, a.y);
                a.z = fmaf(cw, v.z, a.z); a.w = fmaf(cw, v.w, a.w);
            }
        }
    }
    uint2 o;
    o.x = packh2(a.x, a.y);
    o.y = packh2(a.z, a.w);
    *(uint2*)&acc16[(size_t)q * 128 + h * 16 + (ci >> 1)] = o;
}

// ---------------- fused add + layernorm (optional fp16 copy) ----------------
template<bool STORE_HALF>
__global__ __launch_bounds__(256)
void add_ln_kernel(const float* __restrict__ a, const float* __restrict__ b,
                   const float* __restrict__ g, const float* __restrict__ be,
                   float* __restrict__ out, uint32_t* __restrict__ out16, int M)
{
    const int warp = threadIdx.x >> 5;
    const int lane = threadIdx.x & 31;
    const int row  = blockIdx.x * 8 + warp;
    if (row >= M) return;

    const float* ar = a + (size_t)row * 256;
    const float* br = b + (size_t)row * 256;

    float4 v0 = *(const float4*)(ar + lane * 4);
    float4 v1 = *(const float4*)(ar + 128 + lane * 4);
    float4 w0 = *(const float4*)(br + lane * 4);
    float4 w1 = *(const float4*)(br + 128 + lane * 4);

    float v[8];
    v[0] = v0.x + w0.x; v[1] = v0.y + w0.y; v[2] = v0.z + w0.z; v[3] = v0.w + w0.w;
    v[4] = v1.x + w1.x; v[5] = v1.y + w1.y; v[6] = v1.z + w1.z; v[7] = v1.w + w1.w;

    float s = 0.f, sq = 0.f;
#pragma unroll
    for (int i = 0; i < 8; i++) { s += v[i]; sq = fmaf(v[i], v[i], sq); }
#pragma unroll
    for (int o = 16; o; o >>= 1) {
        s  += __shfl_xor_sync(0xffffffffu, s,  o);
        sq += __shfl_xor_sync(0xffffffffu, sq, o);
    }
    const float mean = s * (1.f / 256.f);
    const float var  = sq * (1.f / 256.f) - mean * mean;
    const float inv  = rsqrtf(var + 1e-5f);

    float* orow = out + (size_t)row * 256;
#pragma unroll
    for (int half = 0; half < 2; half++) {
        const int c = half * 128 + lane * 4;
        float4 o;
        float* vv = v + half * 4;
        o.x = (vv[0] - mean) * inv * g[c + 0] + be[c + 0];
        o.y = (vv[1] - mean) * inv * g[c + 1] + be[c + 1];
        o.z = (vv[2] - mean) * inv * g[c + 2] + be[c + 2];
        o.w = (vv[3] - mean) * inv * g[c + 3] + be[c + 3];
        *(float4*)&orow[c] = o;
        if (STORE_HALF) {
            uint2 u;
            u.x = packh2(o.x, o.y);
            u.y = packh2(o.z, o.w);
            *(uint2*)&out16[(size_t)row * 128 + (c >> 1)] = u;
        }
    }
}

// ---------------- launch ----------------
extern "C" void kernel_launch(void* const* d_in, const int* in_sizes, int n_in,
                              void* d_out, int out_size)
{
    const float* src  = (const float*)d_in[0];
    const float* pos  = (const float*)d_in[1];
    const float* ref  = (const float*)d_in[2];
    const float* wv   = (const float*)d_in[3];
    const float* bv   = (const float*)d_in[4];
    const float* wo   = (const float*)d_in[5];
    const float* bo   = (const float*)d_in[6];
    const float* wa   = (const float*)d_in[7];
    const float* ba   = (const float*)d_in[8];
    const float* wout = (const float*)d_in[9];
    const float* bout = (const float*)d_in[10];
    const float* ln1g = (const float*)d_in[11];
    const float* ln1b = (const float*)d_in[12];
    const float* w1   = (const float*)d_in[13];
    const float* b1   = (const float*)d_in[14];
    const float* w2   = (const float*)d_in[15];
    const float* b2   = (const float*)d_in[16];
    const float* ln2g = (const float*)d_in[17];
    const float* ln2b = (const float*)d_in[18];
    float* out = (float*)d_out;

    const int M  = in_sizes[0] / CDIM;       // 26686
    const int mt = (M + 127) / 128;          // 209

    float *value, *offp, *attnp, *src2, *xp, *yp;
    uint32_t *src16, *q16, *acc16, *x16, *h16;
    uint32_t *wvp, *wop, *wap, *woutp, *w1p, *w2p;
    cudaGetSymbolAddress((void**)&value, g_value);
    cudaGetSymbolAddress((void**)&offp,  g_off);
    cudaGetSymbolAddress((void**)&attnp, g_attn);
    cudaGetSymbolAddress((void**)&src2,  g_src2);
    cudaGetSymbolAddress((void**)&xp,    g_x);
    cudaGetSymbolAddress((void**)&yp,    g_y);
    cudaGetSymbolAddress((void**)&src16, g_src16);
    cudaGetSymbolAddress((void**)&q16,   g_q16);
    cudaGetSymbolAddress((void**)&acc16, g_acc16);
    cudaGetSymbolAddress((void**)&x16,   g_x16);
    cudaGetSymbolAddress((void**)&h16,   g_h16);
    cudaGetSymbolAddress((void**)&wvp,   g_wvp);
    cudaGetSymbolAddress((void**)&wop,   g_wop);
    cudaGetSymbolAddress((void**)&wap,   g_wap);
    cudaGetSymbolAddress((void**)&woutp, g_woutp);
    cudaGetSymbolAddress((void**)&w1p,   g_w1p);
    cudaGetSymbolAddress((void**)&w2p,   g_w2p);

    cudaFuncSetAttribute(gemm_h<false, false>, cudaFuncAttributeMaxDynamicSharedMemorySize, SMEM_GEMM);
    cudaFuncSetAttribute(gemm_h<true,  true>,  cudaFuncAttributeMaxDynamicSharedMemorySize, SMEM_GEMM);

    // activation conversions
    const int n2 = M * 128;
    f32_to_h2  <<<(n2 + 255) / 256, 256>>>((const float2*)src, src16, n2);
    addf32_to_h2<<<(n2 + 255) / 256, 256>>>((const float2*)src, (const float2*)pos, q16, n2);
    // weight conversions (pair-interleaved)
    w_to_pairs<<<(128 * 256  + 255) / 256, 256>>>(wv,   wvp,   128,  256);
    w_to_pairs<<<(128 * 320  + 255) / 256, 256>>>(wo,   wop,   128,  320);
    w_to_pairs<<<(128 * 160  + 255) / 256, 256>>>(wa,   wap,   128,  160);
    w_to_pairs<<<(128 * 256  + 255) / 256, 256>>>(wout, woutp, 128,  256);
    w_to_pairs<<<(128 * 2048 + 255) / 256, 256>>>(w1,   w1p,   128,  2048);
    w_to_pairs<<<(1024 * 256 + 255) / 256, 256>>>(w2,   w2p,   1024, 256);

    // 1) value = src @ wv + bv
    gemm_h<false, false><<<dim3(2, mt), 256, SMEM_GEMM>>>((const __half*)src16, wvp, bv, value, M, 256, 256);
    // 2) offsets = q @ wo + bo
    gemm_h<false, false><<<dim3(3, mt), 256, SMEM_GEMM>>>((const __half*)q16, wop, bo, offp, M, 320, 256);
    // 3) attn logits = q @ wa + ba
    gemm_h<false, false><<<dim3(2, mt), 256, SMEM_GEMM>>>((const __half*)q16, wap, ba, attnp, M, 160, 256);
    // 4) deformable sampling -> acc16
    sample_kernel<<<M, 64>>>(value, ref, offp, attnp, acc16);
    // 5) src2 = acc @ wout + bout
    gemm_h<false, false><<<dim3(2, mt), 256, SMEM_GEMM>>>((const __half*)acc16, woutp, bout, src2, M, 256, 256);
    // 6) x = LN(src + src2)  (+ fp16 copy)
    add_ln_kernel<true><<<(M + 7) / 8, 256>>>(src, src2, ln1g, ln1b, xp, x16, M);
    // 7) h = relu(x @ w1 + b1) -> fp16
    gemm_h<true, true><<<dim3(16, mt), 256, SMEM_GEMM>>>((const __half*)x16, w1p, b1, h16, M, 2048, 256);
    // 8) y = h @ w2 + b2
    gemm_h<false, false><<<dim3(2, mt), 256, SMEM_GEMM>>>((const __half*)h16, w2p, b2, yp, M, 256, 2048);
    // 9) out = LN(x + y)
    add_ln_kernel<false><<<(M + 7) / 8, 256>>>(xp, yp, ln2g, ln2b, out, nullptr, M);
}